// round 1
// baseline (speedup 1.0000x reference)
#include <cuda_runtime.h>
#include <math.h>

#define T_TOK 2048
#define DD    1024
#define HH    1024
#define SS    20480
#define KPRUNE 819

// ---------------- scratch (device globals; no allocation allowed) ----------------
__device__ float g_h1[T_TOK * DD];
__device__ float g_h2[T_TOK * DD];
__device__ float g_wtd[T_TOK * DD];
__device__ float g_prefix[(T_TOK + 1) * DD];
__device__ float g_csum[16 * DD];
__device__ float g_Pa[T_TOK * DD];
__device__ float g_Pb[T_TOK * DD];
__device__ float g_Q[(T_TOK + 1) * DD];
__device__ float g_s1[(size_t)SS * HH];
__device__ float g_s2[(size_t)SS * HH];
__device__ float g_zbias[DD];   // zero-initialized

// ---------------- fp32 SGEMM: C = act(A[MxK] @ B[KxN] + bias) ----------------
// BM=BN=128, BK=8, 256 threads, 8x8 per-thread microtile.
template <int RELU>
__global__ __launch_bounds__(256, 2)
void sgemm_kernel(const float* __restrict__ A, const float* __restrict__ B,
                  const float* __restrict__ bias, float* __restrict__ C,
                  int M, int K, int N) {
    __shared__ float As[8][128];
    __shared__ float Bs[8][128];
    const int tid = threadIdx.x;
    const int bm = blockIdx.y * 128;
    const int bn = blockIdx.x * 128;
    const int tx = tid & 15;        // 0..15 (col group)
    const int ty = tid >> 4;        // 0..15 (row group)
    const int aRow = tid >> 1;          // 0..127
    const int aCol = (tid & 1) * 4;     // 0 or 4
    const int bRow = tid >> 5;          // 0..7
    const int bCol = (tid & 31) * 4;    // 0..124

    float acc[8][8];
#pragma unroll
    for (int i = 0; i < 8; i++)
#pragma unroll
        for (int j = 0; j < 8; j++) acc[i][j] = 0.f;

    for (int k0 = 0; k0 < K; k0 += 8) {
        float4 av = make_float4(0.f, 0.f, 0.f, 0.f);
        if (bm + aRow < M)
            av = *(const float4*)&A[(size_t)(bm + aRow) * K + k0 + aCol];
        As[aCol + 0][aRow] = av.x;
        As[aCol + 1][aRow] = av.y;
        As[aCol + 2][aRow] = av.z;
        As[aCol + 3][aRow] = av.w;
        *(float4*)&Bs[bRow][bCol] = *(const float4*)&B[(size_t)(k0 + bRow) * N + bn + bCol];
        __syncthreads();
#pragma unroll
        for (int k = 0; k < 8; k++) {
            float a[8], b[8];
            *(float4*)(a)     = *(float4*)&As[k][ty * 8];
            *(float4*)(a + 4) = *(float4*)&As[k][ty * 8 + 4];
            *(float4*)(b)     = *(float4*)&Bs[k][tx * 8];
            *(float4*)(b + 4) = *(float4*)&Bs[k][tx * 8 + 4];
#pragma unroll
            for (int i = 0; i < 8; i++)
#pragma unroll
                for (int j = 0; j < 8; j++) acc[i][j] += a[i] * b[j];
        }
        __syncthreads();
    }

#pragma unroll
    for (int i = 0; i < 8; i++) {
        int row = bm + ty * 8 + i;
        if (row < M) {
#pragma unroll
            for (int j = 0; j < 8; j++) {
                float v = acc[i][j] + bias[bn + tx * 8 + j];
                if (RELU) v = fmaxf(v, 0.f);
                acc[i][j] = v;
            }
            *(float4*)&C[(size_t)row * N + bn + tx * 8]     = *(float4*)&acc[i][0];
            *(float4*)&C[(size_t)row * N + bn + tx * 8 + 4] = *(float4*)&acc[i][4];
        }
    }
}

// ---------------- softmax over feature dim, times embeds ----------------
__global__ void softmax_mul_kernel(const float* __restrict__ alpha,
                                   const float* __restrict__ emb,
                                   float* __restrict__ wtd) {
    const int r = blockIdx.x;
    const int tid = threadIdx.x;  // 256
    __shared__ float red[256];
    const float4* a4 = (const float4*)(alpha + (size_t)r * DD);
    float4 a = a4[tid];
    float m = fmaxf(fmaxf(a.x, a.y), fmaxf(a.z, a.w));
    red[tid] = m;
    __syncthreads();
    for (int s = 128; s > 0; s >>= 1) {
        if (tid < s) red[tid] = fmaxf(red[tid], red[tid + s]);
        __syncthreads();
    }
    const float mx = red[0];
    __syncthreads();
    float4 e;
    e.x = expf(a.x - mx); e.y = expf(a.y - mx);
    e.z = expf(a.z - mx); e.w = expf(a.w - mx);
    red[tid] = e.x + e.y + e.z + e.w;
    __syncthreads();
    for (int s = 128; s > 0; s >>= 1) {
        if (tid < s) red[tid] += red[tid + s];
        __syncthreads();
    }
    const float inv = 1.f / red[0];
    float4 em = ((const float4*)(emb + (size_t)r * DD))[tid];
    float4 o;
    o.x = e.x * inv * em.x; o.y = e.y * inv * em.y;
    o.z = e.z * inv * em.z; o.w = e.w * inv * em.w;
    ((float4*)(wtd + (size_t)r * DD))[tid] = o;
}

// ---------------- column-wise prefix sum (3 passes) ----------------
__global__ void scan_chunks_kernel(const float* __restrict__ wtd, float* __restrict__ csum) {
    const int c = blockIdx.x;                       // 0..15
    const int col = blockIdx.y * 128 + threadIdx.x; // 0..1023
    float s = 0.f;
#pragma unroll 8
    for (int r = 0; r < 128; r++) s += wtd[(size_t)(c * 128 + r) * DD + col];
    csum[c * DD + col] = s;
}

__global__ void scan_offsets_kernel(float* __restrict__ csum) {
    const int col = blockIdx.x * 256 + threadIdx.x; // 1024 total
    float run = 0.f;
#pragma unroll
    for (int c = 0; c < 16; c++) {
        float t = csum[c * DD + col];
        csum[c * DD + col] = run;
        run += t;
    }
}

__global__ void scan_write_kernel(const float* __restrict__ wtd, const float* __restrict__ csum,
                                  float* __restrict__ prefix) {
    const int c = blockIdx.x;
    const int col = blockIdx.y * 128 + threadIdx.x;
    float run = csum[c * DD + col];
    if (c == 0) prefix[col] = 0.f;
#pragma unroll 8
    for (int r = 0; r < 128; r++) {
        run += wtd[(size_t)(c * 128 + r) * DD + col];
        prefix[(size_t)(c * 128 + r + 1) * DD + col] = run;
    }
}

// ---------------- span assembly: g output + s1 pre-activation ----------------
__global__ void assemble_kernel(const float* __restrict__ L,
                                const int* __restrict__ starts,
                                const int* __restrict__ ends,
                                const float* __restrict__ bs1,
                                float* __restrict__ out_g,
                                float* __restrict__ s1) {
    const int i = blockIdx.x;      // span
    const int t = threadIdx.x;     // 0..255 (float4 index over 1024 features)
    const int s = starts[i];
    const int e = ends[i];
    const float4* L4  = (const float4*)L;
    const float4* pf4 = (const float4*)g_prefix;
    const float4* Pa4 = (const float4*)g_Pa;
    const float4* Pb4 = (const float4*)g_Pb;
    const float4* Q4  = (const float4*)g_Q;

    float4 ls = L4[(size_t)s * 256 + t];
    float4 le = L4[(size_t)e * 256 + t];
    float4 pe = pf4[(size_t)(e + 1) * 256 + t];
    float4 ps = pf4[(size_t)s * 256 + t];
    float4 xa = make_float4(pe.x - ps.x, pe.y - ps.y, pe.z - ps.z, pe.w - ps.w);

    float4* go = (float4*)(out_g + (size_t)i * 3072);
    go[t]       = ls;
    go[256 + t] = le;
    go[512 + t] = xa;

    float4 pa = Pa4[(size_t)s * 256 + t];
    float4 pb = Pb4[(size_t)e * 256 + t];
    float4 qe = Q4[(size_t)(e + 1) * 256 + t];
    float4 qs = Q4[(size_t)s * 256 + t];
    float4 bb = ((const float4*)bs1)[t];
    float4 v;
    v.x = fmaxf(pa.x + pb.x + qe.x - qs.x + bb.x, 0.f);
    v.y = fmaxf(pa.y + pb.y + qe.y - qs.y + bb.y, 0.f);
    v.z = fmaxf(pa.z + pb.z + qe.z - qs.z + bb.z, 0.f);
    v.w = fmaxf(pa.w + pb.w + qe.w - qs.w + bb.w, 0.f);
    ((float4*)s1)[(size_t)i * 256 + t] = v;
}

// ---------------- scores = s2 @ Ws3 + bs3 (one warp per row) ----------------
__global__ void scores_kernel(const float* __restrict__ s2, const float* __restrict__ Ws3,
                              const float* __restrict__ bs3, float* __restrict__ out) {
    const int warp = (blockIdx.x * blockDim.x + threadIdx.x) >> 5;
    const int lane = threadIdx.x & 31;
    if (warp >= SS) return;
    const float4* r4 = (const float4*)(s2 + (size_t)warp * HH);
    const float4* w4 = (const float4*)Ws3;
    float sum = 0.f;
#pragma unroll
    for (int k = lane; k < 256; k += 32) {
        float4 a = r4[k];
        float4 w = w4[k];
        sum += a.x * w.x + a.y * w.y + a.z * w.z + a.w * w.w;
    }
#pragma unroll
    for (int o = 16; o; o >>= 1) sum += __shfl_xor_sync(0xFFFFFFFFu, sum, o);
    if (lane == 0) out[warp] = sum + bs3[0];
}

// ---------------- exact top-k by rank counting (matches jax.lax.top_k) ----------------
__global__ void topk_kernel(const float* __restrict__ scores, float* __restrict__ out_idx) {
    __shared__ float sh[4096];
    const int i = blockIdx.x * 256 + threadIdx.x;   // 80*256 = 20480
    const float my = scores[i];
    int rank = 0;
    for (int c = 0; c < SS; c += 4096) {
#pragma unroll
        for (int j = threadIdx.x; j < 4096; j += 256) sh[j] = scores[c + j];
        __syncthreads();
#pragma unroll 8
        for (int j = 0; j < 4096; j++) {
            float v = sh[j];
            rank += (v > my) ? 1 : ((v == my && (c + j) < i) ? 1 : 0);
        }
        __syncthreads();
    }
    if (rank < KPRUNE) out_idx[rank] = (float)i;
}

// ---------------- launch ----------------
static float* sym_addr(const void* symbol) {
    void* p = nullptr;
    cudaGetSymbolAddress(&p, symbol);
    return (float*)p;
}

extern "C" void kernel_launch(void* const* d_in, const int* in_sizes, int n_in,
                              void* d_out, int out_size) {
    const float* L    = (const float*)d_in[0];
    const float* emb  = (const float*)d_in[1];
    const float* Wa1  = (const float*)d_in[2];
    const float* ba1  = (const float*)d_in[3];
    const float* Wa2  = (const float*)d_in[4];
    const float* ba2  = (const float*)d_in[5];
    const float* Wa3  = (const float*)d_in[6];
    const float* ba3  = (const float*)d_in[7];
    const float* Ws1  = (const float*)d_in[8];
    const float* bs1  = (const float*)d_in[9];
    const float* Ws2  = (const float*)d_in[10];
    const float* bs2  = (const float*)d_in[11];
    const float* Ws3  = (const float*)d_in[12];
    const float* bs3  = (const float*)d_in[13];
    const int* starts = (const int*)d_in[14];
    const int* ends   = (const int*)d_in[15];

    float* out        = (float*)d_out;
    float* out_scores = out;
    float* out_g      = out + SS;
    float* out_idx    = out + SS + (size_t)SS * 3072;

    float* h1  = sym_addr(g_h1);
    float* h2  = sym_addr(g_h2);
    float* wtd = sym_addr(g_wtd);
    float* pfx = sym_addr(g_prefix);
    float* cs  = sym_addr(g_csum);
    float* Pa  = sym_addr(g_Pa);
    float* Pb  = sym_addr(g_Pb);
    float* Q   = sym_addr(g_Q);
    float* s1  = sym_addr(g_s1);
    float* s2  = sym_addr(g_s2);
    float* zb  = sym_addr(g_zbias);

    dim3 gT(DD / 128, T_TOK / 128);          // 8 x 16
    dim3 gQ(DD / 128, (T_TOK + 1 + 127) / 128); // 8 x 17
    dim3 gS2(HH / 128, SS / 128);            // 8 x 160

    // activate path
    sgemm_kernel<1><<<gT, 256>>>(L,  Wa1, ba1, h1, T_TOK, DD, DD);
    sgemm_kernel<1><<<gT, 256>>>(h1, Wa2, ba2, h2, T_TOK, DD, DD);
    sgemm_kernel<0><<<gT, 256>>>(h2, Wa3, ba3, h1, T_TOK, DD, DD);  // alpha -> h1
    softmax_mul_kernel<<<T_TOK, 256>>>(h1, emb, wtd);

    // prefix sums over tokens
    scan_chunks_kernel<<<dim3(16, 8), 128>>>(wtd, cs);
    scan_offsets_kernel<<<4, 256>>>(cs);
    scan_write_kernel<<<dim3(16, 8), 128>>>(wtd, cs, pfx);

    // collapsed first scoring layer: Pa/Pb/Q tables
    sgemm_kernel<0><<<gT, 256>>>(L,   Ws1,                 zb, Pa, T_TOK,     DD, HH);
    sgemm_kernel<0><<<gT, 256>>>(L,   Ws1 + (size_t)DD * HH,     zb, Pb, T_TOK,     DD, HH);
    sgemm_kernel<0><<<gQ, 256>>>(pfx, Ws1 + (size_t)2 * DD * HH, zb, Q,  T_TOK + 1, DD, HH);

    // g output + s1
    assemble_kernel<<<SS, 256>>>(L, starts, ends, bs1, out_g, s1);

    // second scoring layer (dominant GEMM)
    sgemm_kernel<1><<<gS2, 256>>>(s1, Ws2, bs2, s2, SS, HH, HH);

    // scores + exact top-k
    scores_kernel<<<SS / 8, 256>>>(s2, Ws3, bs3, out_scores);
    topk_kernel<<<SS / 256, 256>>>(out_scores, out_idx);
}